// round 14
// baseline (speedup 1.0000x reference)
#include <cuda_runtime.h>
#include <cuda_fp16.h>
#include <cstdint>
#include <math.h>

#define DEPTH   14
#define LEAVES  16384
#define NNODES  32767
#define MEM     512
#define G3      1536
#define WORD    300
#define TAG     100
#define LEAF_IN 400
#define CH_IN   712

// ---------------- scratch (device globals) -----------------------------------
__device__ float  g_Gi[(size_t)LEAVES * G3];            // right-child preacts (odd rows), fp32
__device__ float  g_H32 [(size_t)(LEAVES / 2) * MEM];   // h1 fp32
__device__ float  g_H232[(size_t)(LEAVES / 2) * MEM];   // h2 fp32
__device__ __half g_states16[(size_t)NNODES * MEM];
__device__ __half g_H16 [(size_t)(LEAVES / 2) * MEM];
__device__ __half g_H216[(size_t)(LEAVES / 2) * MEM];
__device__ __half g_leafx16[(size_t)LEAVES * LEAF_IN];
__device__ __half g_tagp16[(size_t)NNODES * (2 * TAG)];
__device__ __half g_Wl16 [(size_t)G3 * LEAF_IN];
__device__ __half g_Wci16[(size_t)G3 * CH_IN];
__device__ __half g_Wch16[(size_t)G3 * MEM];
__device__ __half g_Wn16 [(size_t)G3 * MEM];

__device__ __forceinline__ float sigmoidf(float x) { return 1.0f / (1.0f + expf(-x)); }

__device__ __forceinline__ void mma_f16(float* c, const uint32_t* a, const uint32_t* b) {
    asm volatile(
        "mma.sync.aligned.m16n8k16.row.col.f32.f16.f16.f32 "
        "{%0,%1,%2,%3}, {%4,%5,%6,%7}, {%8,%9}, {%0,%1,%2,%3};"
        : "+f"(c[0]), "+f"(c[1]), "+f"(c[2]), "+f"(c[3])
        : "r"(a[0]), "r"(a[1]), "r"(a[2]), "r"(a[3]), "r"(b[0]), "r"(b[1]));
}
__device__ __forceinline__ void ldsm4(uint32_t* r, uint32_t addr) {
    asm volatile("ldmatrix.sync.aligned.m8n8.x4.shared.b16 {%0,%1,%2,%3}, [%4];"
                 : "=r"(r[0]), "=r"(r[1]), "=r"(r[2]), "=r"(r[3]) : "r"(addr));
}
__device__ __forceinline__ void ldsm2(uint32_t* r, uint32_t addr) {
    asm volatile("ldmatrix.sync.aligned.m8n8.x2.shared.b16 {%0,%1}, [%2];"
                 : "=r"(r[0]), "=r"(r[1]) : "r"(addr));
}
__device__ __forceinline__ uint32_t smem_u32(const void* p) {
    uint32_t a;
    asm("{ .reg .u64 t; cvta.to.shared.u64 t, %1; cvt.u32.u64 %0, t; }" : "=r"(a) : "l"(p));
    return a;
}
__device__ __forceinline__ void cp16(uint32_t dst, const void* src, int sz) {
    asm volatile("cp.async.cg.shared.global [%0], [%1], 16, %2;"
                 :: "r"(dst), "l"(src), "r"(sz) : "memory");
}
#define CP_COMMIT() asm volatile("cp.async.commit_group;" ::: "memory")
#define CP_WAIT1()  asm volatile("cp.async.wait_group 1;" ::: "memory")

// ---------------- shared epilogue ------------------------------------------------
template<int MODE>
__device__ __forceinline__ void gru_epilogue(
        int row, int kcol, int M, int nlvl, float aR, float aZ, float aN,
        const float* __restrict__ bi, const float* __restrict__ bh,
        float* __restrict__ out) {
    if (row >= M) return;
    if (MODE == 0) {
        float r  = sigmoidf(aR + bi[kcol] + bh[kcol]);
        float z  = sigmoidf(aZ + bi[MEM + kcol] + bh[MEM + kcol]);
        float nn = tanhf(aN + bi[2 * MEM + kcol] + r * bh[2 * MEM + kcol]);
        g_states16[(size_t)(LEAVES - 1 + row) * MEM + kcol] = __float2half((1.0f - z) * nn);
    } else if (MODE == 1) {
        float giR = aR + bi[kcol], giZ = aZ + bi[MEM + kcol], giN = aN + bi[2 * MEM + kcol];
        if ((row & 1) == 0) {
            float r  = sigmoidf(giR + bh[kcol]);
            float z  = sigmoidf(giZ + bh[MEM + kcol]);
            float nn = tanhf(giN + r * bh[2 * MEM + kcol]);
            float h1 = (1.0f - z) * nn;
            size_t idx = (size_t)(row >> 1) * MEM + kcol;
            g_H32[idx] = h1;
            g_H16[idx] = __float2half(h1);
        } else {
            float* d = g_Gi + (size_t)row * G3;
            d[kcol] = giR; d[MEM + kcol] = giZ; d[2 * MEM + kcol] = giN;
        }
    } else if (MODE == 2) {
        const float* gi = g_Gi + (size_t)(2 * row + 1) * G3;
        float r  = sigmoidf(gi[kcol] + aR + bh[kcol]);
        float z  = sigmoidf(gi[MEM + kcol] + aZ + bh[MEM + kcol]);
        float nn = tanhf(gi[2 * MEM + kcol] + r * (aN + bh[2 * MEM + kcol]));
        size_t idx = (size_t)row * MEM + kcol;
        float h2 = (1.0f - z) * nn + z * g_H32[idx];
        g_H232[idx] = h2;
        g_H216[idx] = __float2half(h2);
    } else {
        float r  = sigmoidf(bi[kcol] + aR + bh[kcol]);
        float z  = sigmoidf(bi[MEM + kcol] + aZ + bh[MEM + kcol]);
        float nn = tanhf(bi[2 * MEM + kcol] + r * (aN + bh[2 * MEM + kcol]));
        float st = (1.0f - z) * nn + z * g_H232[(size_t)row * MEM + kcol];
        g_states16[(size_t)(row + nlvl - 1) * MEM + kcol] = __float2half(st);
        if (nlvl == 1) out[kcol] = st;
    }
}

// ---------------- A-tile cp.async source resolver --------------------------------
template<int MODE>
__device__ __forceinline__ void resolveA(int gm, int e, int M, int nlvl,
                                         const void*& p, int& sz) {
    p = g_leafx16; sz = 0;
    if (MODE == 0) {
        if (gm < M && e < LEAF_IN) { p = g_leafx16 + (size_t)gm * LEAF_IN + e; sz = 16; }
    } else if (MODE == 1) {
        if (gm < M) {
            int pid = (gm >> 1) + nlvl - 1;
            int ch  = 2 * pid + 1 + (gm & 1);
            if (e < MEM)        { p = g_states16 + (size_t)ch * MEM + e; sz = 16; }
            else if (e < CH_IN) { p = g_tagp16 + (size_t)ch * (2 * TAG) + (e - MEM); sz = 16; }
        }
    } else {
        const __half* src = (MODE == 2) ? g_H16 : g_H216;
        if (gm < M && e < MEM) { p = src + (size_t)gm * MEM + e; sz = 16; }
    }
}

// =============== SMALL kernel: 64 x 32 tile, 3 CTAs/SM (R13, proven) ==============
#define S_STAGE  23040u
#define S_BOFF   9216u
#define S_SMEM   (3 * 23040)

template<int MODE, int K>
__global__ __launch_bounds__(256, 3)
void gemm_small(const __half* __restrict__ Wr, const float* __restrict__ bi,
                const float* __restrict__ bh, int M, int nlvl, float* __restrict__ out) {
    extern __shared__ float sm[];
    constexpr int NC = (K + 63) / 64;
    const int tid  = threadIdx.x;
    const int lane = tid & 31;
    const int wid  = tid >> 5;
    const int gID  = lane >> 2, tq = lane & 3;
    const int wmRow = (wid >> 2) * 32;
    const int wk    = (wid & 3) * 8;
    const int gk0   = blockIdx.x * 32;
    const int bm    = blockIdx.y * 64;

    float acc[2][3][4];
    #pragma unroll
    for (int a = 0; a < 2; a++)
        #pragma unroll
        for (int b = 0; b < 3; b++)
            #pragma unroll
            for (int c = 0; c < 4; c++) acc[a][b][c] = 0.0f;

    const uint32_t smem_base = smem_u32(sm);
    const int rA0 = tid >> 3;
    const int eq  = (tid & 7) * 8;
    const uint32_t dstA0 = smem_base + (uint32_t)(rA0 * 144 + (tid & 7) * 16);
    const uint32_t dstB0 = smem_base + S_BOFF + (uint32_t)(rA0 * 144 + (tid & 7) * 16);
    uint32_t offB[3];
    #pragma unroll
    for (int it = 0; it < 3; it++) {
        int rB = rA0 + 32 * it;
        int grow = (rB >> 5) * MEM + gk0 + (rB & 31);
        offB[it] = (uint32_t)grow * K + eq;
    }
    uint32_t aAddr[2];
    #pragma unroll
    for (int mt = 0; mt < 2; mt++)
        aAddr[mt] = smem_base + (uint32_t)((wmRow + mt * 16 + (lane & 15)) * 144 + (lane >> 4) * 16);
    uint32_t bAddr[3];
    #pragma unroll
    for (int g = 0; g < 3; g++)
        bAddr[g] = smem_base + S_BOFF +
                   (uint32_t)((g * 32 + wk + (lane & 7)) * 144 + (((lane >> 3) & 1) * 16));

    auto issueA = [&](int kc, uint32_t stN) {
        #pragma unroll
        for (int it = 0; it < 2; it++) {
            const void* p; int sz;
            resolveA<MODE>(bm + rA0 + 32 * it, kc * 64 + eq, M, nlvl, p, sz);
            cp16(dstA0 + stN + it * 4608u, p, sz);
        }
    };
    auto issueB = [&](int kc, uint32_t stN) {
        const int sz = (kc * 64 + eq < K) ? 16 : 0;
        #pragma unroll
        for (int it = 0; it < 3; it++)
            cp16(dstB0 + stN + it * 4608u, Wr + offB[it] + (uint32_t)kc * 64u, sz);
    };

    issueA(0, 0u); issueB(0, 0u); CP_COMMIT();
    if (NC > 1) { issueA(1, S_STAGE); issueB(1, S_STAGE); }
    CP_COMMIT();

    uint32_t stC = 0, stI = 2 * S_STAGE;
    #pragma unroll 1
    for (int kc = 0; kc < NC; kc++) {
        CP_WAIT1();
        __syncthreads();
        if (kc + 2 < NC) { issueA(kc + 2, stI); issueB(kc + 2, stI); }
        CP_COMMIT();
        #pragma unroll
        for (int k16 = 0; k16 < 4; k16++) {
            const uint32_t kb = stC + k16 * 32u;
            uint32_t afr[2][4], bfr[3][2];
            ldsm4(afr[0], aAddr[0] + kb);
            ldsm4(afr[1], aAddr[1] + kb);
            ldsm2(bfr[0], bAddr[0] + kb);
            ldsm2(bfr[1], bAddr[1] + kb);
            ldsm2(bfr[2], bAddr[2] + kb);
            #pragma unroll
            for (int mt = 0; mt < 2; mt++)
                #pragma unroll
                for (int g = 0; g < 3; g++)
                    mma_f16(acc[mt][g], afr[mt], bfr[g]);
        }
        stC += S_STAGE; if (stC == 3 * S_STAGE) stC = 0;
        stI += S_STAGE; if (stI == 3 * S_STAGE) stI = 0;
    }

    #pragma unroll
    for (int mt = 0; mt < 2; mt++)
        #pragma unroll
        for (int j = 0; j < 4; j++)
            gru_epilogue<MODE>(bm + wmRow + mt * 16 + gID + (j >> 1) * 8,
                               gk0 + wk + 2 * tq + (j & 1), M, nlvl,
                               acc[mt][0][j], acc[mt][1][j], acc[mt][2][j], bi, bh, out);
}

// =============== BIG kernel: 128 x 32 tile, 2 CTAs/SM ============================
// A 128x144B + B 96x144B per stage = 32256B; 3 stages = 96768B.
// 8 warps: (wid>>1) = row group (32 rows), (wid&1) = col group (16 cols).
#define B_BOFF   18432u
#define B_STAGE  32256u
#define B_SMEM   (3 * 32256)

template<int MODE, int K>
__global__ __launch_bounds__(256, 2)
void gemm_big(const __half* __restrict__ Wr, const float* __restrict__ bi,
              const float* __restrict__ bh, int M, int nlvl, float* __restrict__ out) {
    extern __shared__ float sm[];
    constexpr int NC = (K + 63) / 64;
    const int tid  = threadIdx.x;
    const int lane = tid & 31;
    const int wid  = tid >> 5;
    const int gID  = lane >> 2, tq = lane & 3;
    const int wmRow = (wid >> 1) * 32;         // 0/32/64/96
    const int wk    = (wid & 1) * 16;          // 0/16
    const int gk0   = blockIdx.x * 32;
    const int bm    = blockIdx.y * 128;

    float acc[2][6][4];                        // [mt][g*2+kt][j]
    #pragma unroll
    for (int a = 0; a < 2; a++)
        #pragma unroll
        for (int b = 0; b < 6; b++)
            #pragma unroll
            for (int c = 0; c < 4; c++) acc[a][b][c] = 0.0f;

    const uint32_t smem_base = smem_u32(sm);
    const int rA0 = tid >> 3;
    const int eq  = (tid & 7) * 8;
    const uint32_t dstA0 = smem_base + (uint32_t)(rA0 * 144 + (tid & 7) * 16);
    const uint32_t dstB0 = smem_base + B_BOFF + (uint32_t)(rA0 * 144 + (tid & 7) * 16);
    uint32_t offB[3];
    #pragma unroll
    for (int it = 0; it < 3; it++) {
        int rB = rA0 + 32 * it;
        int grow = (rB >> 5) * MEM + gk0 + (rB & 31);
        offB[it] = (uint32_t)grow * K + eq;
    }
    uint32_t aAddr[2];
    #pragma unroll
    for (int mt = 0; mt < 2; mt++)
        aAddr[mt] = smem_base + (uint32_t)((wmRow + mt * 16 + (lane & 15)) * 144 + (lane >> 4) * 16);
    uint32_t bAddr[3];
    #pragma unroll
    for (int g = 0; g < 3; g++)
        bAddr[g] = smem_base + B_BOFF +
                   (uint32_t)((g * 32 + wk + ((lane >> 4) << 3) + (lane & 7)) * 144 +
                              (((lane >> 3) & 1) * 16));

    auto issueA = [&](int kc, uint32_t stN) {
        #pragma unroll
        for (int it = 0; it < 4; it++) {
            const void* p; int sz;
            resolveA<MODE>(bm + rA0 + 32 * it, kc * 64 + eq, M, nlvl, p, sz);
            cp16(dstA0 + stN + it * 4608u, p, sz);
        }
    };
    auto issueB = [&](int kc, uint32_t stN) {
        const int sz = (kc * 64 + eq < K) ? 16 : 0;
        #pragma unroll
        for (int it = 0; it < 3; it++)
            cp16(dstB0 + stN + it * 4608u, Wr + offB[it] + (uint32_t)kc * 64u, sz);
    };

    issueA(0, 0u); issueB(0, 0u); CP_COMMIT();
    if (NC > 1) { issueA(1, B_STAGE); issueB(1, B_STAGE); }
    CP_COMMIT();

    uint32_t stC = 0, stI = 2 * B_STAGE;
    #pragma unroll 1
    for (int kc = 0; kc < NC; kc++) {
        CP_WAIT1();
        __syncthreads();
        if (kc + 2 < NC) { issueA(kc + 2, stI); issueB(kc + 2, stI); }
        CP_COMMIT();
        #pragma unroll
        for (int k16 = 0; k16 < 4; k16++) {
            const uint32_t kb = stC + k16 * 32u;
            uint32_t afr[2][4], bfr[3][4];
            ldsm4(afr[0], aAddr[0] + kb);
            ldsm4(afr[1], aAddr[1] + kb);
            ldsm4(bfr[0], bAddr[0] + kb);
            ldsm4(bfr[1], bAddr[1] + kb);
            ldsm4(bfr[2], bAddr[2] + kb);
            #pragma unroll
            for (int mt = 0; mt < 2; mt++)
                #pragma unroll
                for (int g = 0; g < 3; g++) {
                    mma_f16(acc[mt][2 * g],     afr[mt], bfr[g]);
                    mma_f16(acc[mt][2 * g + 1], afr[mt], bfr[g] + 2);
                }
        }
        stC += B_STAGE; if (stC == 3 * B_STAGE) stC = 0;
        stI += B_STAGE; if (stI == 3 * B_STAGE) stI = 0;
    }

    #pragma unroll
    for (int mt = 0; mt < 2; mt++)
        #pragma unroll
        for (int kt = 0; kt < 2; kt++)
            #pragma unroll
            for (int j = 0; j < 4; j++)
                gru_epilogue<MODE>(bm + wmRow + mt * 16 + gID + (j >> 1) * 8,
                                   gk0 + wk + kt * 8 + 2 * tq + (j & 1), M, nlvl,
                                   acc[mt][kt][j], acc[mt][2 + kt][j], acc[mt][4 + kt][j],
                                   bi, bh, out);
}

// ---------------- prep: build fp16 operands ------------------------------------
__global__ void prep_half(const float* __restrict__ embs, const float* __restrict__ tags,
                          const float* __restrict__ lw, const float* __restrict__ cwi,
                          const float* __restrict__ cwh, const float* __restrict__ nw) {
    const int64_t stride = (int64_t)gridDim.x * blockDim.x;
    const int64_t t0 = blockIdx.x * (int64_t)blockDim.x + threadIdx.x;
    for (int64_t i = t0; i < (int64_t)LEAVES * LEAF_IN; i += stride) {
        int r = (int)(i / LEAF_IN), c = (int)(i % LEAF_IN);
        float v = (c < WORD) ? embs[(size_t)r * WORD + c]
                             : tags[(size_t)(LEAVES - 1 + r) * TAG + (c - WORD)];
        g_leafx16[i] = __float2half(v);
    }
    for (int64_t i = t0; i < (int64_t)NNODES * 2 * TAG; i += stride) {
        int id = (int)(i / (2 * TAG)), c = (int)(i % (2 * TAG));
        int pid = (id > 0) ? ((id - 1) >> 1) : 0;
        float v = (c < TAG) ? tags[(size_t)id * TAG + c]
                            : tags[(size_t)pid * TAG + (c - TAG)];
        g_tagp16[i] = __float2half(v);
    }
    for (int64_t i = t0; i < (int64_t)G3 * LEAF_IN; i += stride) g_Wl16[i]  = __float2half(lw[i]);
    for (int64_t i = t0; i < (int64_t)G3 * CH_IN;  i += stride) g_Wci16[i] = __float2half(cwi[i]);
    for (int64_t i = t0; i < (int64_t)G3 * MEM;    i += stride) g_Wch16[i] = __float2half(cwh[i]);
    for (int64_t i = t0; i < (int64_t)G3 * MEM;    i += stride) g_Wn16[i]  = __float2half(nw[i]);
}

// ---------------- host driver ------------------------------------------------
extern "C" void kernel_launch(void* const* d_in, const int* in_sizes, int n_in,
                              void* d_out, int out_size) {
    const float* embs    = (const float*)d_in[0];
    const float* tags    = (const float*)d_in[1];
    const float* leaf_Wi = (const float*)d_in[2];
    const float* leaf_bi = (const float*)d_in[4];
    const float* leaf_bh = (const float*)d_in[5];
    const float* node_Wh = (const float*)d_in[7];
    const float* node_bi = (const float*)d_in[8];
    const float* node_bh = (const float*)d_in[9];
    const float* ch_Wi   = (const float*)d_in[10];
    const float* ch_Wh   = (const float*)d_in[11];
    const float* ch_bi   = (const float*)d_in[12];
    const float* ch_bh   = (const float*)d_in[13];

    __half *pWl, *pWci, *pWch, *pWn;
    cudaGetSymbolAddress((void**)&pWl,  g_Wl16);
    cudaGetSymbolAddress((void**)&pWci, g_Wci16);
    cudaGetSymbolAddress((void**)&pWch, g_Wch16);
    cudaGetSymbolAddress((void**)&pWn,  g_Wn16);

    cudaFuncSetAttribute(gemm_small<1,CH_IN>, cudaFuncAttributeMaxDynamicSharedMemorySize, S_SMEM);
    cudaFuncSetAttribute(gemm_small<2,MEM>,   cudaFuncAttributeMaxDynamicSharedMemorySize, S_SMEM);
    cudaFuncSetAttribute(gemm_small<3,MEM>,   cudaFuncAttributeMaxDynamicSharedMemorySize, S_SMEM);
    cudaFuncSetAttribute(gemm_big<0,LEAF_IN>, cudaFuncAttributeMaxDynamicSharedMemorySize, B_SMEM);
    cudaFuncSetAttribute(gemm_big<1,CH_IN>,   cudaFuncAttributeMaxDynamicSharedMemorySize, B_SMEM);
    cudaFuncSetAttribute(gemm_big<2,MEM>,     cudaFuncAttributeMaxDynamicSharedMemorySize, B_SMEM);
    cudaFuncSetAttribute(gemm_big<3,MEM>,     cudaFuncAttributeMaxDynamicSharedMemorySize, B_SMEM);

    float* out = (float*)d_out;
    auto gridB = [](int M) { return dim3(MEM / 32, (M + 127) / 128); };
    auto gridS = [](int M) { return dim3(MEM / 32, (M + 63) / 64); };

    prep_half<<<1024, 256>>>(embs, tags, leaf_Wi, ch_Wi, ch_Wh, node_Wh);

    gemm_big<0,LEAF_IN><<<gridB(LEAVES), 256, B_SMEM>>>(pWl, leaf_bi, leaf_bh, LEAVES, 0, out);
    for (int lvl = DEPTH - 1; lvl >= 0; --lvl) {
        int n = 1 << lvl;
        if (2 * n >= 256)
            gemm_big<1,CH_IN><<<gridB(2 * n), 256, B_SMEM>>>(pWci, ch_bi, ch_bh, 2 * n, n, out);
        else
            gemm_small<1,CH_IN><<<gridS(2 * n), 256, S_SMEM>>>(pWci, ch_bi, ch_bh, 2 * n, n, out);
        if (n >= 256) {
            gemm_big<2,MEM><<<gridB(n), 256, B_SMEM>>>(pWch, ch_bi, ch_bh, n, n, out);
            gemm_big<3,MEM><<<gridB(n), 256, B_SMEM>>>(pWn, node_bi, node_bh, n, n, out);
        } else {
            gemm_small<2,MEM><<<gridS(n), 256, S_SMEM>>>(pWch, ch_bi, ch_bh, n, n, out);
            gemm_small<3,MEM><<<gridS(n), 256, S_SMEM>>>(pWn, node_bi, node_bh, n, n, out);
        }
    }
}

// round 15
// speedup vs baseline: 1.0399x; 1.0399x over previous
#include <cuda_runtime.h>
#include <cuda_fp16.h>
#include <cstdint>
#include <math.h>

#define DEPTH   14
#define LEAVES  16384
#define NNODES  32767
#define MEM     512
#define G3      1536
#define WORD    300
#define TAG     100
#define LEAF_IN 400
#define CH_IN   712

// ---------------- scratch (device globals) -----------------------------------
__device__ __half g_Gi16[(size_t)LEAVES * G3];          // right-child preacts (odd rows), fp16
__device__ float  g_H32 [(size_t)(LEAVES / 2) * MEM];   // h1 fp32
__device__ float  g_H232[(size_t)(LEAVES / 2) * MEM];   // h2 fp32
__device__ __half g_states16[(size_t)NNODES * MEM];
__device__ __half g_H16 [(size_t)(LEAVES / 2) * MEM];
__device__ __half g_H216[(size_t)(LEAVES / 2) * MEM];
__device__ __half g_leafx16[(size_t)LEAVES * LEAF_IN];
__device__ __half g_tagp16[(size_t)NNODES * (2 * TAG)];
__device__ __half g_Wl16 [(size_t)G3 * LEAF_IN];
__device__ __half g_Wci16[(size_t)G3 * CH_IN];
__device__ __half g_Wch16[(size_t)G3 * MEM];
__device__ __half g_Wn16 [(size_t)G3 * MEM];

__device__ __forceinline__ float sigmoidf(float x) { return 1.0f / (1.0f + __expf(-x)); }
__device__ __forceinline__ float tanh_apx(float x) {
    float y;
    asm("tanh.approx.f32 %0, %1;" : "=f"(y) : "f"(x));
    return y;
}

__device__ __forceinline__ void mma_f16(float* c, const uint32_t* a, const uint32_t* b) {
    asm volatile(
        "mma.sync.aligned.m16n8k16.row.col.f32.f16.f16.f32 "
        "{%0,%1,%2,%3}, {%4,%5,%6,%7}, {%8,%9}, {%0,%1,%2,%3};"
        : "+f"(c[0]), "+f"(c[1]), "+f"(c[2]), "+f"(c[3])
        : "r"(a[0]), "r"(a[1]), "r"(a[2]), "r"(a[3]), "r"(b[0]), "r"(b[1]));
}
__device__ __forceinline__ void ldsm4(uint32_t* r, uint32_t addr) {
    asm volatile("ldmatrix.sync.aligned.m8n8.x4.shared.b16 {%0,%1,%2,%3}, [%4];"
                 : "=r"(r[0]), "=r"(r[1]), "=r"(r[2]), "=r"(r[3]) : "r"(addr));
}
__device__ __forceinline__ void ldsm2(uint32_t* r, uint32_t addr) {
    asm volatile("ldmatrix.sync.aligned.m8n8.x2.shared.b16 {%0,%1}, [%2];"
                 : "=r"(r[0]), "=r"(r[1]) : "r"(addr));
}
__device__ __forceinline__ uint32_t smem_u32(const void* p) {
    uint32_t a;
    asm("{ .reg .u64 t; cvta.to.shared.u64 t, %1; cvt.u32.u64 %0, t; }" : "=r"(a) : "l"(p));
    return a;
}
__device__ __forceinline__ void cp16(uint32_t dst, const void* src, int sz) {
    asm volatile("cp.async.cg.shared.global [%0], [%1], 16, %2;"
                 :: "r"(dst), "l"(src), "r"(sz) : "memory");
}
#define CP_COMMIT() asm volatile("cp.async.commit_group;" ::: "memory")
#define CP_WAIT1()  asm volatile("cp.async.wait_group 1;" ::: "memory")

// ---------------- fused GEMM + GRU kernel: 64 x 32-gate-col tile ----------------
// B tile = W rows {k, 512+k, 1024+k} for 32 kcols -> 96 rows; A tile 64 rows.
// BK = 64 halves (128 B + 16 pad = 144 B row stride). 3 stages, 3 CTAs/SM.
// MODE: 0=leaf, 1=ch_Wi (h1 even / gi odd), 2=ch_Wh (h2), 3=node_Wh (states).
#define STAGE_B  23040u                 // (64 + 96) rows * 144 B
#define BOFF     9216u                  // A region = 64 * 144
#define SMEM_SZ  (3 * 23040)

template<int MODE, int K>
__global__ __launch_bounds__(256, 3)
void gemm_gru(const __half* __restrict__ Wr, const float* __restrict__ bi,
              const float* __restrict__ bh, int M, int nlvl, float* __restrict__ out) {
    extern __shared__ float sm[];
    constexpr int NC = (K + 63) / 64;

    const int tid  = threadIdx.x;
    const int lane = tid & 31;
    const int wid  = tid >> 5;
    const int gID  = lane >> 2, tq = lane & 3;
    const int wmRow = (wid >> 2) * 32;         // 0 / 32
    const int wk    = (wid & 3) * 8;           // 0..24 within 32 gate-cols
    const int gk0   = blockIdx.x * 32;
    const int bm    = blockIdx.y * 64;

    float acc[2][3][4];
    #pragma unroll
    for (int a = 0; a < 2; a++)
        #pragma unroll
        for (int b = 0; b < 3; b++)
            #pragma unroll
            for (int c = 0; c < 4; c++) acc[a][b][c] = 0.0f;

    const uint32_t smem_base = smem_u32(sm);
    const int rA0 = tid >> 3;                  // 0..31
    const int eq  = (tid & 7) * 8;             // half-offset within 64-half chunk
    const uint32_t dstA0 = smem_base + (uint32_t)(rA0 * 144 + (tid & 7) * 16);
    const uint32_t dstB0 = smem_base + BOFF + (uint32_t)(rA0 * 144 + (tid & 7) * 16);
    uint32_t offB[3];
    #pragma unroll
    for (int it = 0; it < 3; it++) {
        int rB = rA0 + 32 * it;                // 0..95
        int grow = (rB >> 5) * MEM + gk0 + (rB & 31);
        offB[it] = (uint32_t)grow * K + eq;
    }

    uint32_t aAddr[2];
    #pragma unroll
    for (int mt = 0; mt < 2; mt++)
        aAddr[mt] = smem_base + (uint32_t)((wmRow + mt * 16 + (lane & 15)) * 144 + (lane >> 4) * 16);
    // B: gates 0+1 via one ldsm.x4 (lanes 0-15 -> gate0, 16-31 -> gate1); gate 2 via ldsm.x2
    const uint32_t bAddr01 = smem_base + BOFF +
        (uint32_t)(((lane >> 4) * 32 + wk + (lane & 7)) * 144 + (((lane >> 3) & 1) * 16));
    const uint32_t bAddr2 = smem_base + BOFF +
        (uint32_t)((2 * 32 + wk + (lane & 7)) * 144 + (((lane >> 3) & 1) * 16));

    auto issueA = [&](int kc, uint32_t stN) {
        #pragma unroll
        for (int it = 0; it < 2; it++) {
            const int e  = kc * 64 + eq;
            const int gm = bm + rA0 + 32 * it;
            const void* p = g_leafx16;
            int sz = 0;
            if (MODE == 0) {
                if (gm < M && e < LEAF_IN) { p = g_leafx16 + (size_t)gm * LEAF_IN + e; sz = 16; }
            } else if (MODE == 1) {
                if (gm < M) {
                    int pid = (gm >> 1) + nlvl - 1;
                    int ch  = 2 * pid + 1 + (gm & 1);
                    if (e < MEM)        { p = g_states16 + (size_t)ch * MEM + e; sz = 16; }
                    else if (e < CH_IN) { p = g_tagp16 + (size_t)ch * (2 * TAG) + (e - MEM); sz = 16; }
                }
            } else {
                const __half* src = (MODE == 2) ? g_H16 : g_H216;
                if (gm < M && e < MEM) { p = src + (size_t)gm * MEM + e; sz = 16; }
            }
            cp16(dstA0 + stN + it * 4608u, p, sz);
        }
    };
    auto issueB = [&](int kc, uint32_t stN) {
        const int e = kc * 64 + eq;
        const int sz = (e < K) ? 16 : 0;
        #pragma unroll
        for (int it = 0; it < 3; it++)
            cp16(dstB0 + stN + it * 4608u, Wr + offB[it] + (uint32_t)kc * 64u, sz);
    };

    issueA(0, 0u); issueB(0, 0u); CP_COMMIT();
    if (NC > 1) { issueA(1, STAGE_B); issueB(1, STAGE_B); }
    CP_COMMIT();

    uint32_t stC = 0, stI = 2 * STAGE_B;
    #pragma unroll 1
    for (int kc = 0; kc < NC; kc++) {
        CP_WAIT1();
        __syncthreads();
        if (kc + 2 < NC) { issueA(kc + 2, stI); issueB(kc + 2, stI); }
        CP_COMMIT();
        #pragma unroll
        for (int k16 = 0; k16 < 4; k16++) {        // 4 x k16 = 64 halves
            const uint32_t kb = stC + k16 * 32u;
            uint32_t afr[2][4], b01[4], b2[2];
            ldsm4(afr[0], aAddr[0] + kb);
            ldsm4(afr[1], aAddr[1] + kb);
            ldsm4(b01, bAddr01 + kb);              // gates 0 & 1
            ldsm2(b2,  bAddr2 + kb);               // gate 2
            #pragma unroll
            for (int mt = 0; mt < 2; mt++) {
                mma_f16(acc[mt][0], afr[mt], b01);
                mma_f16(acc[mt][1], afr[mt], b01 + 2);
                mma_f16(acc[mt][2], afr[mt], b2);
            }
        }
        stC += STAGE_B; if (stC == 3 * STAGE_B) stC = 0;
        stI += STAGE_B; if (stI == 3 * STAGE_B) stI = 0;
    }

    // ---- fused epilogue ----
    #pragma unroll
    for (int mt = 0; mt < 2; mt++)
        #pragma unroll
        for (int j = 0; j < 4; j++) {
            int row = bm + wmRow + mt * 16 + gID + (j >> 1) * 8;
            if (row >= M) continue;
            int kcol = gk0 + wk + 2 * tq + (j & 1);
            float aR = acc[mt][0][j];
            float aZ = acc[mt][1][j];
            float aN = acc[mt][2][j];
            if (MODE == 0) {
                float r  = sigmoidf(aR + bi[kcol] + bh[kcol]);
                float z  = sigmoidf(aZ + bi[MEM + kcol] + bh[MEM + kcol]);
                float nn = tanh_apx(aN + bi[2 * MEM + kcol] + r * bh[2 * MEM + kcol]);
                g_states16[(size_t)(LEAVES - 1 + row) * MEM + kcol] =
                    __float2half((1.0f - z) * nn);
            } else if (MODE == 1) {
                float giR = aR + bi[kcol], giZ = aZ + bi[MEM + kcol],
                      giN = aN + bi[2 * MEM + kcol];
                if ((row & 1) == 0) {
                    float r  = sigmoidf(giR + bh[kcol]);
                    float z  = sigmoidf(giZ + bh[MEM + kcol]);
                    float nn = tanh_apx(giN + r * bh[2 * MEM + kcol]);
                    float h1 = (1.0f - z) * nn;
                    size_t idx = (size_t)(row >> 1) * MEM + kcol;
                    g_H32[idx] = h1;
                    g_H16[idx] = __float2half(h1);
                } else {
                    __half* d = g_Gi16 + (size_t)row * G3;
                    d[kcol] = __float2half(giR);
                    d[MEM + kcol] = __float2half(giZ);
                    d[2 * MEM + kcol] = __float2half(giN);
                }
            } else if (MODE == 2) {
                const __half* gi = g_Gi16 + (size_t)(2 * row + 1) * G3;
                float r  = sigmoidf(__half2float(gi[kcol]) + aR + bh[kcol]);
                float z  = sigmoidf(__half2float(gi[MEM + kcol]) + aZ + bh[MEM + kcol]);
                float nn = tanh_apx(__half2float(gi[2 * MEM + kcol]) +
                                    r * (aN + bh[2 * MEM + kcol]));
                size_t idx = (size_t)row * MEM + kcol;
                float h2 = (1.0f - z) * nn + z * g_H32[idx];
                g_H232[idx] = h2;
                g_H216[idx] = __float2half(h2);
            } else {
                float r  = sigmoidf(bi[kcol] + aR + bh[kcol]);
                float z  = sigmoidf(bi[MEM + kcol] + aZ + bh[MEM + kcol]);
                float nn = tanh_apx(bi[2 * MEM + kcol] + r * (aN + bh[2 * MEM + kcol]));
                float st = (1.0f - z) * nn + z * g_H232[(size_t)row * MEM + kcol];
                g_states16[(size_t)(row + nlvl - 1) * MEM + kcol] = __float2half(st);
                if (nlvl == 1) out[kcol] = st;
            }
        }
}

// ---------------- prep: build fp16 operands ------------------------------------
__global__ void prep_half(const float* __restrict__ embs, const float* __restrict__ tags,
                          const float* __restrict__ lw, const float* __restrict__ cwi,
                          const float* __restrict__ cwh, const float* __restrict__ nw) {
    const int64_t stride = (int64_t)gridDim.x * blockDim.x;
    const int64_t t0 = blockIdx.x * (int64_t)blockDim.x + threadIdx.x;
    for (int64_t i = t0; i < (int64_t)LEAVES * LEAF_IN; i += stride) {
        int r = (int)(i / LEAF_IN), c = (int)(i % LEAF_IN);
        float v = (c < WORD) ? embs[(size_t)r * WORD + c]
                             : tags[(size_t)(LEAVES - 1 + r) * TAG + (c - WORD)];
        g_leafx16[i] = __float2half(v);
    }
    for (int64_t i = t0; i < (int64_t)NNODES * 2 * TAG; i += stride) {
        int id = (int)(i / (2 * TAG)), c = (int)(i % (2 * TAG));
        int pid = (id > 0) ? ((id - 1) >> 1) : 0;
        float v = (c < TAG) ? tags[(size_t)id * TAG + c]
                            : tags[(size_t)pid * TAG + (c - TAG)];
        g_tagp16[i] = __float2half(v);
    }
    for (int64_t i = t0; i < (int64_t)G3 * LEAF_IN; i += stride) g_Wl16[i]  = __float2half(lw[i]);
    for (int64_t i = t0; i < (int64_t)G3 * CH_IN;  i += stride) g_Wci16[i] = __float2half(cwi[i]);
    for (int64_t i = t0; i < (int64_t)G3 * MEM;    i += stride) g_Wch16[i] = __float2half(cwh[i]);
    for (int64_t i = t0; i < (int64_t)G3 * MEM;    i += stride) g_Wn16[i]  = __float2half(nw[i]);
}

// ---------------- host driver ------------------------------------------------
extern "C" void kernel_launch(void* const* d_in, const int* in_sizes, int n_in,
                              void* d_out, int out_size) {
    const float* embs    = (const float*)d_in[0];
    const float* tags    = (const float*)d_in[1];
    const float* leaf_Wi = (const float*)d_in[2];
    const float* leaf_bi = (const float*)d_in[4];
    const float* leaf_bh = (const float*)d_in[5];
    const float* node_Wh = (const float*)d_in[7];
    const float* node_bi = (const float*)d_in[8];
    const float* node_bh = (const float*)d_in[9];
    const float* ch_Wi   = (const float*)d_in[10];
    const float* ch_Wh   = (const float*)d_in[11];
    const float* ch_bi   = (const float*)d_in[12];
    const float* ch_bh   = (const float*)d_in[13];

    __half *pWl, *pWci, *pWch, *pWn;
    cudaGetSymbolAddress((void**)&pWl,  g_Wl16);
    cudaGetSymbolAddress((void**)&pWci, g_Wci16);
    cudaGetSymbolAddress((void**)&pWch, g_Wch16);
    cudaGetSymbolAddress((void**)&pWn,  g_Wn16);

    cudaFuncSetAttribute(gemm_gru<0,LEAF_IN>, cudaFuncAttributeMaxDynamicSharedMemorySize, SMEM_SZ);
    cudaFuncSetAttribute(gemm_gru<1,CH_IN>,   cudaFuncAttributeMaxDynamicSharedMemorySize, SMEM_SZ);
    cudaFuncSetAttribute(gemm_gru<2,MEM>,     cudaFuncAttributeMaxDynamicSharedMemorySize, SMEM_SZ);
    cudaFuncSetAttribute(gemm_gru<3,MEM>,     cudaFuncAttributeMaxDynamicSharedMemorySize, SMEM_SZ);

    auto grid = [](int M) { return dim3(MEM / 32, (M + 63) / 64); };
    float* out = (float*)d_out;

    prep_half<<<1024, 256>>>(embs, tags, leaf_Wi, ch_Wi, ch_Wh, node_Wh);

    gemm_gru<0,LEAF_IN><<<grid(LEAVES), 256, SMEM_SZ>>>(pWl, leaf_bi, leaf_bh, LEAVES, 0, out);
    for (int lvl = DEPTH - 1; lvl >= 0; --lvl) {
        int n = 1 << lvl;
        gemm_gru<1,CH_IN><<<grid(2 * n), 256, SMEM_SZ>>>(pWci, ch_bi, ch_bh, 2 * n, n, out);
        gemm_gru<2,MEM><<<grid(n), 256, SMEM_SZ>>>(pWch, ch_bi, ch_bh, n, n, out);
        gemm_gru<3,MEM><<<grid(n), 256, SMEM_SZ>>>(pWn, node_bi, node_bh, n, n, out);
    }
}

// round 16
// speedup vs baseline: 1.0633x; 1.0225x over previous
#include <cuda_runtime.h>
#include <cuda_fp16.h>
#include <cstdint>
#include <math.h>

#define DEPTH   14
#define LEAVES  16384
#define NNODES  32767
#define MEM     512
#define G3      1536
#define WORD    300
#define TAG     100
#define LEAF_IN 400
#define CH_IN   712

// ---------------- scratch (device globals) -----------------------------------
__device__ __half g_Gi16[(size_t)LEAVES * G3];          // right-child preacts (odd rows), fp16
__device__ float  g_H32 [(size_t)(LEAVES / 2) * MEM];   // h1 fp32
__device__ float  g_H232[(size_t)(LEAVES / 2) * MEM];   // h2 fp32
__device__ __half g_states16[(size_t)NNODES * MEM];
__device__ __half g_H16 [(size_t)(LEAVES / 2) * MEM];
__device__ __half g_H216[(size_t)(LEAVES / 2) * MEM];
__device__ __half g_leafx16[(size_t)LEAVES * LEAF_IN];
__device__ __half g_tagp16[(size_t)NNODES * (2 * TAG)];
__device__ __half g_Wl16 [(size_t)G3 * LEAF_IN];
__device__ __half g_Wci16[(size_t)G3 * CH_IN];
__device__ __half g_Wch16[(size_t)G3 * MEM];
__device__ __half g_Wn16 [(size_t)G3 * MEM];

__device__ __forceinline__ float sigmoidf(float x) { return 1.0f / (1.0f + __expf(-x)); }
__device__ __forceinline__ float tanh_apx(float x) {
    float y;
    asm("tanh.approx.f32 %0, %1;" : "=f"(y) : "f"(x));
    return y;
}

__device__ __forceinline__ void mma_f16(float* c, const uint32_t* a, const uint32_t* b) {
    asm volatile(
        "mma.sync.aligned.m16n8k16.row.col.f32.f16.f16.f32 "
        "{%0,%1,%2,%3}, {%4,%5,%6,%7}, {%8,%9}, {%0,%1,%2,%3};"
        : "+f"(c[0]), "+f"(c[1]), "+f"(c[2]), "+f"(c[3])
        : "r"(a[0]), "r"(a[1]), "r"(a[2]), "r"(a[3]), "r"(b[0]), "r"(b[1]));
}
__device__ __forceinline__ void ldsm4(uint32_t* r, uint32_t addr) {
    asm volatile("ldmatrix.sync.aligned.m8n8.x4.shared.b16 {%0,%1,%2,%3}, [%4];"
                 : "=r"(r[0]), "=r"(r[1]), "=r"(r[2]), "=r"(r[3]) : "r"(addr));
}
__device__ __forceinline__ void ldsm2(uint32_t* r, uint32_t addr) {
    asm volatile("ldmatrix.sync.aligned.m8n8.x2.shared.b16 {%0,%1}, [%2];"
                 : "=r"(r[0]), "=r"(r[1]) : "r"(addr));
}
__device__ __forceinline__ uint32_t smem_u32(const void* p) {
    uint32_t a;
    asm("{ .reg .u64 t; cvta.to.shared.u64 t, %1; cvt.u32.u64 %0, t; }" : "=r"(a) : "l"(p));
    return a;
}
__device__ __forceinline__ void cp16(uint32_t dst, const void* src, int sz) {
    asm volatile("cp.async.cg.shared.global [%0], [%1], 16, %2;"
                 :: "r"(dst), "l"(src), "r"(sz) : "memory");
}
#define CP_COMMIT() asm volatile("cp.async.commit_group;" ::: "memory")
#define CP_WAIT1()  asm volatile("cp.async.wait_group 1;" ::: "memory")

// ---------------- fused GEMM + GRU kernel: 64 x 32-gate-col tile ----------------
// B tile = W rows {k, 512+k, 1024+k} for 32 kcols -> 96 rows; A tile 64 rows.
// BK = 64 halves (128 B + 16 pad = 144 B row stride). 3 stages, 3 CTAs/SM.
// MODE: 0=leaf, 1=ch_Wi (h1 even / gi odd), 2=ch_Wh (h2), 3=node_Wh (states).
// PDL: weights (B) prefetched pre-sync for MODE!=0; A / gi / h_prev post-sync.
#define STAGE_B  23040u                 // (64 + 96) rows * 144 B
#define BOFF     9216u                  // A region = 64 * 144
#define SMEM_SZ  (3 * 23040)

template<int MODE, int K>
__global__ __launch_bounds__(256, 3)
void gemm_gru(const __half* __restrict__ Wr, const float* __restrict__ bi,
              const float* __restrict__ bh, int M, int nlvl, float* __restrict__ out) {
    extern __shared__ float sm[];
    constexpr int NC = (K + 63) / 64;

    const int tid  = threadIdx.x;
    const int lane = tid & 31;
    const int wid  = tid >> 5;
    const int gID  = lane >> 2, tq = lane & 3;
    const int wmRow = (wid >> 2) * 32;         // 0 / 32
    const int wk    = (wid & 3) * 8;           // 0..24 within 32 gate-cols
    const int gk0   = blockIdx.x * 32;
    const int bm    = blockIdx.y * 64;

    float acc[2][3][4];
    #pragma unroll
    for (int a = 0; a < 2; a++)
        #pragma unroll
        for (int b = 0; b < 3; b++)
            #pragma unroll
            for (int c = 0; c < 4; c++) acc[a][b][c] = 0.0f;

    const uint32_t smem_base = smem_u32(sm);
    const int rA0 = tid >> 3;                  // 0..31
    const int eq  = (tid & 7) * 8;             // half-offset within 64-half chunk
    const uint32_t dstA0 = smem_base + (uint32_t)(rA0 * 144 + (tid & 7) * 16);
    const uint32_t dstB0 = smem_base + BOFF + (uint32_t)(rA0 * 144 + (tid & 7) * 16);
    uint32_t offB[3];
    #pragma unroll
    for (int it = 0; it < 3; it++) {
        int rB = rA0 + 32 * it;                // 0..95
        int grow = (rB >> 5) * MEM + gk0 + (rB & 31);
        offB[it] = (uint32_t)grow * K + eq;
    }

    uint32_t aAddr[2];
    #pragma unroll
    for (int mt = 0; mt < 2; mt++)
        aAddr[mt] = smem_base + (uint32_t)((wmRow + mt * 16 + (lane & 15)) * 144 + (lane >> 4) * 16);
    // B: gates 0+1 via one ldsm.x4 (lanes 0-15 -> gate0, 16-31 -> gate1); gate 2 via ldsm.x2
    const uint32_t bAddr01 = smem_base + BOFF +
        (uint32_t)(((lane >> 4) * 32 + wk + (lane & 7)) * 144 + (((lane >> 3) & 1) * 16));
    const uint32_t bAddr2 = smem_base + BOFF +
        (uint32_t)((2 * 32 + wk + (lane & 7)) * 144 + (((lane >> 3) & 1) * 16));

    auto issueA = [&](int kc, uint32_t stN) {
        #pragma unroll
        for (int it = 0; it < 2; it++) {
            const int e  = kc * 64 + eq;
            const int gm = bm + rA0 + 32 * it;
            const void* p = g_leafx16;
            int sz = 0;
            if (MODE == 0) {
                if (gm < M && e < LEAF_IN) { p = g_leafx16 + (size_t)gm * LEAF_IN + e; sz = 16; }
            } else if (MODE == 1) {
                if (gm < M) {
                    int pid = (gm >> 1) + nlvl - 1;
                    int ch  = 2 * pid + 1 + (gm & 1);
                    if (e < MEM)        { p = g_states16 + (size_t)ch * MEM + e; sz = 16; }
                    else if (e < CH_IN) { p = g_tagp16 + (size_t)ch * (2 * TAG) + (e - MEM); sz = 16; }
                }
            } else {
                const __half* src = (MODE == 2) ? g_H16 : g_H216;
                if (gm < M && e < MEM) { p = src + (size_t)gm * MEM + e; sz = 16; }
            }
            cp16(dstA0 + stN + it * 4608u, p, sz);
        }
    };
    auto issueB = [&](int kc, uint32_t stN) {
        const int e = kc * 64 + eq;
        const int sz = (e < K) ? 16 : 0;
        #pragma unroll
        for (int it = 0; it < 3; it++)
            cp16(dstB0 + stN + it * 4608u, Wr + offB[it] + (uint32_t)kc * 64u, sz);
    };

    // ---- PDL prologue: prefetch weights before the dependency sync --------------
    if (MODE != 0) {                       // weights written by prep (>=2 kernels back)
        issueB(0, 0u);
        if (NC > 1) issueB(1, STAGE_B);
    }
    cudaGridDependencySynchronize();       // wait for predecessor's dependent data
    if (MODE == 0) {                       // leaf: weights come from immediate pred (prep)
        issueB(0, 0u);
        if (NC > 1) issueB(1, STAGE_B);
    }
    issueA(0, 0u); CP_COMMIT();            // group0 = B0[,B1] + A0
    if (NC > 1) issueA(1, STAGE_B);
    CP_COMMIT();                           // group1 = A1

    uint32_t stC = 0, stI = 2 * STAGE_B;
    #pragma unroll 1
    for (int kc = 0; kc < NC; kc++) {
        CP_WAIT1();
        __syncthreads();
        if (kc + 2 < NC) { issueA(kc + 2, stI); issueB(kc + 2, stI); }
        CP_COMMIT();
        #pragma unroll
        for (int k16 = 0; k16 < 4; k16++) {        // 4 x k16 = 64 halves
            const uint32_t kb = stC + k16 * 32u;
            uint32_t afr[2][4], b01[4], b2[2];
            ldsm4(afr[0], aAddr[0] + kb);
            ldsm4(afr[1], aAddr[1] + kb);
            ldsm4(b01, bAddr01 + kb);              // gates 0 & 1
            ldsm2(b2,  bAddr2 + kb);               // gate 2
            #pragma unroll
            for (int mt = 0; mt < 2; mt++) {
                mma_f16(acc[mt][0], afr[mt], b01);
                mma_f16(acc[mt][1], afr[mt], b01 + 2);
                mma_f16(acc[mt][2], afr[mt], b2);
            }
        }
        stC += STAGE_B; if (stC == 3 * STAGE_B) stC = 0;
        stI += STAGE_B; if (stI == 3 * STAGE_B) stI = 0;
    }

    // ---- fused epilogue ----
    #pragma unroll
    for (int mt = 0; mt < 2; mt++)
        #pragma unroll
        for (int j = 0; j < 4; j++) {
            int row = bm + wmRow + mt * 16 + gID + (j >> 1) * 8;
            if (row >= M) continue;
            int kcol = gk0 + wk + 2 * tq + (j & 1);
            float aR = acc[mt][0][j];
            float aZ = acc[mt][1][j];
            float aN = acc[mt][2][j];
            if (MODE == 0) {
                float r  = sigmoidf(aR + bi[kcol] + bh[kcol]);
                float z  = sigmoidf(aZ + bi[MEM + kcol] + bh[MEM + kcol]);
                float nn = tanh_apx(aN + bi[2 * MEM + kcol] + r * bh[2 * MEM + kcol]);
                g_states16[(size_t)(LEAVES - 1 + row) * MEM + kcol] =
                    __float2half((1.0f - z) * nn);
            } else if (MODE == 1) {
                float giR = aR + bi[kcol], giZ = aZ + bi[MEM + kcol],
                      giN = aN + bi[2 * MEM + kcol];
                if ((row & 1) == 0) {
                    float r  = sigmoidf(giR + bh[kcol]);
                    float z  = sigmoidf(giZ + bh[MEM + kcol]);
                    float nn = tanh_apx(giN + r * bh[2 * MEM + kcol]);
                    float h1 = (1.0f - z) * nn;
                    size_t idx = (size_t)(row >> 1) * MEM + kcol;
                    g_H32[idx] = h1;
                    g_H16[idx] = __float2half(h1);
                } else {
                    __half* d = g_Gi16 + (size_t)row * G3;
                    d[kcol] = __float2half(giR);
                    d[MEM + kcol] = __float2half(giZ);
                    d[2 * MEM + kcol] = __float2half(giN);
                }
            } else if (MODE == 2) {
                const __half* gi = g_Gi16 + (size_t)(2 * row + 1) * G3;
                float r  = sigmoidf(__half2float(gi[kcol]) + aR + bh[kcol]);
                float z  = sigmoidf(__half2float(gi[MEM + kcol]) + aZ + bh[MEM + kcol]);
                float nn = tanh_apx(__half2float(gi[2 * MEM + kcol]) +
                                    r * (aN + bh[2 * MEM + kcol]));
                size_t idx = (size_t)row * MEM + kcol;
                float h2 = (1.0f - z) * nn + z * g_H32[idx];
                g_H232[idx] = h2;
                g_H216[idx] = __float2half(h2);
            } else {
                float r  = sigmoidf(bi[kcol] + aR + bh[kcol]);
                float z  = sigmoidf(bi[MEM + kcol] + aZ + bh[MEM + kcol]);
                float nn = tanh_apx(bi[2 * MEM + kcol] + r * (aN + bh[2 * MEM + kcol]));
                float st = (1.0f - z) * nn + z * g_H232[(size_t)row * MEM + kcol];
                g_states16[(size_t)(row + nlvl - 1) * MEM + kcol] = __float2half(st);
                if (nlvl == 1) out[kcol] = st;
            }
        }

    // All dependent stores issued above -> allow successor to start.
    cudaTriggerProgrammaticLaunchCompletion();
}

// ---------------- prep: build fp16 operands ------------------------------------
__global__ void prep_half(const float* __restrict__ embs, const float* __restrict__ tags,
                          const float* __restrict__ lw, const float* __restrict__ cwi,
                          const float* __restrict__ cwh, const float* __restrict__ nw) {
    const int64_t stride = (int64_t)gridDim.x * blockDim.x;
    const int64_t t0 = blockIdx.x * (int64_t)blockDim.x + threadIdx.x;
    for (int64_t i = t0; i < (int64_t)LEAVES * LEAF_IN; i += stride) {
        int r = (int)(i / LEAF_IN), c = (int)(i % LEAF_IN);
        float v = (c < WORD) ? embs[(size_t)r * WORD + c]
                             : tags[(size_t)(LEAVES - 1 + r) * TAG + (c - WORD)];
        g_leafx16[i] = __float2half(v);
    }
    for (int64_t i = t0; i < (int64_t)NNODES * 2 * TAG; i += stride) {
        int id = (int)(i / (2 * TAG)), c = (int)(i % (2 * TAG));
        int pid = (id > 0) ? ((id - 1) >> 1) : 0;
        float v = (c < TAG) ? tags[(size_t)id * TAG + c]
                            : tags[(size_t)pid * TAG + (c - TAG)];
        g_tagp16[i] = __float2half(v);
    }
    for (int64_t i = t0; i < (int64_t)G3 * LEAF_IN; i += stride) g_Wl16[i]  = __float2half(lw[i]);
    for (int64_t i = t0; i < (int64_t)G3 * CH_IN;  i += stride) g_Wci16[i] = __float2half(cwi[i]);
    for (int64_t i = t0; i < (int64_t)G3 * MEM;    i += stride) g_Wch16[i] = __float2half(cwh[i]);
    for (int64_t i = t0; i < (int64_t)G3 * MEM;    i += stride) g_Wn16[i]  = __float2half(nw[i]);
    cudaTriggerProgrammaticLaunchCompletion();
}

// ---------------- host driver ------------------------------------------------
template<typename F, typename... Args>
static void launch_pdl(F f, dim3 g, dim3 b, size_t smem, Args... args) {
    cudaLaunchConfig_t cfg = {};
    cfg.gridDim = g;
    cfg.blockDim = b;
    cfg.dynamicSmemBytes = smem;
    cfg.stream = 0;
    cudaLaunchAttribute attr[1];
    attr[0].id = cudaLaunchAttributeProgrammaticStreamSerialization;
    attr[0].val.programmaticStreamSerializationAllowed = 1;
    cfg.attrs = attr;
    cfg.numAttrs = 1;
    cudaLaunchKernelEx(&cfg, f, args...);
}

extern "C" void kernel_launch(void* const* d_in, const int* in_sizes, int n_in,
                              void* d_out, int out_size) {
    const float* embs    = (const float*)d_in[0];
    const float* tags    = (const float*)d_in[1];
    const float* leaf_Wi = (const float*)d_in[2];
    const float* leaf_bi = (const float*)d_in[4];
    const float* leaf_bh = (const float*)d_in[5];
    const float* node_Wh = (const float*)d_in[7];
    const float* node_bi = (const float*)d_in[8];
    const float* node_bh = (const float*)d_in[9];
    const float* ch_Wi   = (const float*)d_in[10];
    const float* ch_Wh   = (const float*)d_in[11];
    const float* ch_bi   = (const float*)d_in[12];
    const float* ch_bh   = (const float*)d_in[13];

    __half *pWl, *pWci, *pWch, *pWn;
    cudaGetSymbolAddress((void**)&pWl,  g_Wl16);
    cudaGetSymbolAddress((void**)&pWci, g_Wci16);
    cudaGetSymbolAddress((void**)&pWch, g_Wch16);
    cudaGetSymbolAddress((void**)&pWn,  g_Wn16);

    cudaFuncSetAttribute(gemm_gru<0,LEAF_IN>, cudaFuncAttributeMaxDynamicSharedMemorySize, SMEM_SZ);
    cudaFuncSetAttribute(gemm_gru<1,CH_IN>,   cudaFuncAttributeMaxDynamicSharedMemorySize, SMEM_SZ);
    cudaFuncSetAttribute(gemm_gru<2,MEM>,     cudaFuncAttributeMaxDynamicSharedMemorySize, SMEM_SZ);
    cudaFuncSetAttribute(gemm_gru<3,MEM>,     cudaFuncAttributeMaxDynamicSharedMemorySize, SMEM_SZ);

    auto grid = [](int M) { return dim3(MEM / 32, (M + 63) / 64); };
    float* out = (float*)d_out;

    prep_half<<<1024, 256>>>(embs, tags, leaf_Wi, ch_Wi, ch_Wh, node_Wh);

    launch_pdl(gemm_gru<0,LEAF_IN>, grid(LEAVES), dim3(256), SMEM_SZ,
               (const __half*)pWl, leaf_bi, leaf_bh, LEAVES, 0, out);
    for (int lvl = DEPTH - 1; lvl >= 0; --lvl) {
        int n = 1 << lvl;
        launch_pdl(gemm_gru<1,CH_IN>, grid(2 * n), dim3(256), SMEM_SZ,
                   (const __half*)pWci, ch_bi, ch_bh, 2 * n, n, out);
        launch_pdl(gemm_gru<2,MEM>, grid(n), dim3(256), SMEM_SZ,
                   (const __half*)pWch, ch_bi, ch_bh, n, n, out);
        launch_pdl(gemm_gru<3,MEM>, grid(n), dim3(256), SMEM_SZ,
                   (const __half*)pWn, node_bi, node_bh, n, n, out);
    }
}

// round 17
// speedup vs baseline: 1.2532x; 1.1786x over previous
#include <cuda_runtime.h>
#include <cuda_fp16.h>
#include <cstdint>
#include <math.h>

#define DEPTH   14
#define LEAVES  16384
#define NNODES  32767
#define MEM     512
#define G3      1536
#define WORD    300
#define TAG     100
#define LEAF_IN 400
#define CH_IN   712

// ---------------- scratch (device globals) -----------------------------------
__device__ __half g_Gi16[(size_t)LEAVES * G3];          // right-child preacts (odd rows), fp16
__device__ float  g_H32 [(size_t)(LEAVES / 2) * MEM];   // h1 fp32
__device__ float  g_H232[(size_t)(LEAVES / 2) * MEM];   // h2 fp32
__device__ __half g_states16[(size_t)NNODES * MEM];
__device__ __half g_H16 [(size_t)(LEAVES / 2) * MEM];
__device__ __half g_H216[(size_t)(LEAVES / 2) * MEM];
__device__ __half g_leafx16[(size_t)LEAVES * LEAF_IN];
__device__ __half g_tagp16[(size_t)NNODES * (2 * TAG)];
__device__ __half g_Wl16 [(size_t)G3 * LEAF_IN];
__device__ __half g_Wci16[(size_t)G3 * CH_IN];
__device__ __half g_Wch16[(size_t)G3 * MEM];
__device__ __half g_Wn16 [(size_t)G3 * MEM];

__device__ __forceinline__ float sigmoidf(float x) { return 1.0f / (1.0f + __expf(-x)); }
__device__ __forceinline__ float tanh_apx(float x) {
    float y;
    asm("tanh.approx.f32 %0, %1;" : "=f"(y) : "f"(x));
    return y;
}

__device__ __forceinline__ void mma_f16(float* c, const uint32_t* a, const uint32_t* b) {
    asm volatile(
        "mma.sync.aligned.m16n8k16.row.col.f32.f16.f16.f32 "
        "{%0,%1,%2,%3}, {%4,%5,%6,%7}, {%8,%9}, {%0,%1,%2,%3};"
        : "+f"(c[0]), "+f"(c[1]), "+f"(c[2]), "+f"(c[3])
        : "r"(a[0]), "r"(a[1]), "r"(a[2]), "r"(a[3]), "r"(b[0]), "r"(b[1]));
}
__device__ __forceinline__ void ldsm4(uint32_t* r, uint32_t addr) {
    asm volatile("ldmatrix.sync.aligned.m8n8.x4.shared.b16 {%0,%1,%2,%3}, [%4];"
                 : "=r"(r[0]), "=r"(r[1]), "=r"(r[2]), "=r"(r[3]) : "r"(addr));
}
__device__ __forceinline__ void ldsm2(uint32_t* r, uint32_t addr) {
    asm volatile("ldmatrix.sync.aligned.m8n8.x2.shared.b16 {%0,%1}, [%2];"
                 : "=r"(r[0]), "=r"(r[1]) : "r"(addr));
}
__device__ __forceinline__ uint32_t smem_u32(const void* p) {
    uint32_t a;
    asm("{ .reg .u64 t; cvta.to.shared.u64 t, %1; cvt.u32.u64 %0, t; }" : "=r"(a) : "l"(p));
    return a;
}
__device__ __forceinline__ void cp16(uint32_t dst, const void* src, int sz) {
    asm volatile("cp.async.cg.shared.global [%0], [%1], 16, %2;"
                 :: "r"(dst), "l"(src), "r"(sz) : "memory");
}
#define CP_COMMIT() asm volatile("cp.async.commit_group;" ::: "memory")
#define CP_WAIT1()  asm volatile("cp.async.wait_group 1;" ::: "memory")

// ---------------- fused GEMM + GRU kernel: 64 x 32-gate-col tile ----------------
// B tile = W rows {k, 512+k, 1024+k} for 32 kcols -> 96 rows; A tile 64 rows.
// BK = 64 halves (128 B + 16 pad = 144 B row stride). 3 stages, 3 CTAs/SM.
// MODE: 0=leaf, 1=ch_Wi (h1 even / gi odd), 2=ch_Wh (h2), 3=node_Wh (states).
#define STAGE_B  23040u                 // (64 + 96) rows * 144 B
#define BOFF     9216u                  // A region = 64 * 144
#define SMEM_SZ  (3 * 23040)

template<int MODE, int K>
__global__ __launch_bounds__(256, 3)
void gemm_gru(const __half* __restrict__ Wr, const float* __restrict__ bi,
              const float* __restrict__ bh, int M, int nlvl, float* __restrict__ out) {
    extern __shared__ float sm[];
    constexpr int NC = (K + 63) / 64;

    const int tid  = threadIdx.x;
    const int lane = tid & 31;
    const int wid  = tid >> 5;
    const int gID  = lane >> 2, tq = lane & 3;
    const int wmRow = (wid >> 2) * 32;         // 0 / 32
    const int wk    = (wid & 3) * 8;           // 0..24 within 32 gate-cols
    const int gk0   = blockIdx.x * 32;
    const int bm    = blockIdx.y * 64;

    float acc[2][3][4];
    #pragma unroll
    for (int a = 0; a < 2; a++)
        #pragma unroll
        for (int b = 0; b < 3; b++)
            #pragma unroll
            for (int c = 0; c < 4; c++) acc[a][b][c] = 0.0f;

    const uint32_t smem_base = smem_u32(sm);
    const int rA0 = tid >> 3;                  // 0..31
    const int eq  = (tid & 7) * 8;             // half-offset within 64-half chunk
    const uint32_t dstA0 = smem_base + (uint32_t)(rA0 * 144 + (tid & 7) * 16);
    const uint32_t dstB0 = smem_base + BOFF + (uint32_t)(rA0 * 144 + (tid & 7) * 16);
    uint32_t offB[3];
    #pragma unroll
    for (int it = 0; it < 3; it++) {
        int rB = rA0 + 32 * it;                // 0..95
        int grow = (rB >> 5) * MEM + gk0 + (rB & 31);
        offB[it] = (uint32_t)grow * K + eq;
    }

    uint32_t aAddr[2];
    #pragma unroll
    for (int mt = 0; mt < 2; mt++)
        aAddr[mt] = smem_base + (uint32_t)((wmRow + mt * 16 + (lane & 15)) * 144 + (lane >> 4) * 16);
    const uint32_t bAddr01 = smem_base + BOFF +
        (uint32_t)(((lane >> 4) * 32 + wk + (lane & 7)) * 144 + (((lane >> 3) & 1) * 16));
    const uint32_t bAddr2 = smem_base + BOFF +
        (uint32_t)((2 * 32 + wk + (lane & 7)) * 144 + (((lane >> 3) & 1) * 16));

    auto issueA = [&](int kc, uint32_t stN) {
        #pragma unroll
        for (int it = 0; it < 2; it++) {
            const int e  = kc * 64 + eq;
            const int gm = bm + rA0 + 32 * it;
            const void* p = g_leafx16;
            int sz = 0;
            if (MODE == 0) {
                if (gm < M && e < LEAF_IN) { p = g_leafx16 + (size_t)gm * LEAF_IN + e; sz = 16; }
            } else if (MODE == 1) {
                if (gm < M) {
                    int pid = (gm >> 1) + nlvl - 1;
                    int ch  = 2 * pid + 1 + (gm & 1);
                    if (e < MEM)        { p = g_states16 + (size_t)ch * MEM + e; sz = 16; }
                    else if (e < CH_IN) { p = g_tagp16 + (size_t)ch * (2 * TAG) + (e - MEM); sz = 16; }
                }
            } else {
                const __half* src = (MODE == 2) ? g_H16 : g_H216;
                if (gm < M && e < MEM) { p = src + (size_t)gm * MEM + e; sz = 16; }
            }
            cp16(dstA0 + stN + it * 4608u, p, sz);
        }
    };
    auto issueB = [&](int kc, uint32_t stN) {
        const int e = kc * 64 + eq;
        const int sz = (e < K) ? 16 : 0;
        #pragma unroll
        for (int it = 0; it < 3; it++)
            cp16(dstB0 + stN + it * 4608u, Wr + offB[it] + (uint32_t)kc * 64u, sz);
    };

    // ---- PDL prologue: prefetch weights before the dependency sync --------------
    if (MODE != 0) {
        issueB(0, 0u);
        if (NC > 1) issueB(1, STAGE_B);
    }
    cudaGridDependencySynchronize();
    if (MODE == 0) {
        issueB(0, 0u);
        if (NC > 1) issueB(1, STAGE_B);
    }
    issueA(0, 0u); CP_COMMIT();
    if (NC > 1) issueA(1, STAGE_B);
    CP_COMMIT();

    uint32_t stC = 0, stI = 2 * STAGE_B;
    #pragma unroll 1
    for (int kc = 0; kc < NC; kc++) {
        CP_WAIT1();
        __syncthreads();
        uint32_t afr[2][2][4];
        uint32_t b01[4], b2[2];
        // k16 = 0: load A(0), B(0); prefetch A(1)
        ldsm4(afr[0][0], aAddr[0] + stC);
        ldsm4(afr[0][1], aAddr[1] + stC);
        ldsm4(b01, bAddr01 + stC);
        ldsm2(b2,  bAddr2  + stC);
        ldsm4(afr[1][0], aAddr[0] + stC + 32u);
        ldsm4(afr[1][1], aAddr[1] + stC + 32u);
        #pragma unroll
        for (int mt = 0; mt < 2; mt++) {
            mma_f16(acc[mt][0], afr[0][mt], b01);
            mma_f16(acc[mt][1], afr[0][mt], b01 + 2);
            mma_f16(acc[mt][2], afr[0][mt], b2);
        }
        // next-stage cp.async overlaps with tensor work
        if (kc + 2 < NC) { issueA(kc + 2, stI); issueB(kc + 2, stI); }
        CP_COMMIT();
        #pragma unroll
        for (int k16 = 1; k16 < 4; k16++) {
            const uint32_t kb = stC + k16 * 32u;
            const int cur = k16 & 1;
            ldsm4(b01, bAddr01 + kb);
            ldsm2(b2,  bAddr2  + kb);
            if (k16 < 3) {
                ldsm4(afr[cur ^ 1][0], aAddr[0] + kb + 32u);
                ldsm4(afr[cur ^ 1][1], aAddr[1] + kb + 32u);
            }
            #pragma unroll
            for (int mt = 0; mt < 2; mt++) {
                mma_f16(acc[mt][0], afr[cur][mt], b01);
                mma_f16(acc[mt][1], afr[cur][mt], b01 + 2);
                mma_f16(acc[mt][2], afr[cur][mt], b2);
            }
        }
        stC += STAGE_B; if (stC == 3 * STAGE_B) stC = 0;
        stI += STAGE_B; if (stI == 3 * STAGE_B) stI = 0;
    }

    // ---- fused epilogue (vectorized: kcol pairs) ---------------------------------
    const int kc0 = gk0 + wk + 2 * tq;        // even -> float2/half2 aligned
    #pragma unroll
    for (int mt = 0; mt < 2; mt++)
        #pragma unroll
        for (int j2 = 0; j2 < 2; j2++) {
            int row = bm + wmRow + mt * 16 + gID + j2 * 8;
            if (row >= M) continue;
            float aR0 = acc[mt][0][j2 * 2], aR1 = acc[mt][0][j2 * 2 + 1];
            float aZ0 = acc[mt][1][j2 * 2], aZ1 = acc[mt][1][j2 * 2 + 1];
            float aN0 = acc[mt][2][j2 * 2], aN1 = acc[mt][2][j2 * 2 + 1];
            float2 bhR = *(const float2*)(bh + kc0);
            float2 bhZ = *(const float2*)(bh + MEM + kc0);
            float2 bhN = *(const float2*)(bh + 2 * MEM + kc0);
            if (MODE == 0) {
                float2 biR = *(const float2*)(bi + kc0);
                float2 biZ = *(const float2*)(bi + MEM + kc0);
                float2 biN = *(const float2*)(bi + 2 * MEM + kc0);
                float r0 = sigmoidf(aR0 + biR.x + bhR.x), r1 = sigmoidf(aR1 + biR.y + bhR.y);
                float z0 = sigmoidf(aZ0 + biZ.x + bhZ.x), z1 = sigmoidf(aZ1 + biZ.y + bhZ.y);
                float n0 = tanh_apx(aN0 + biN.x + r0 * bhN.x);
                float n1 = tanh_apx(aN1 + biN.y + r1 * bhN.y);
                *(__half2*)(g_states16 + (size_t)(LEAVES - 1 + row) * MEM + kc0) =
                    __floats2half2_rn((1.0f - z0) * n0, (1.0f - z1) * n1);
            } else if (MODE == 1) {
                float2 biR = *(const float2*)(bi + kc0);
                float2 biZ = *(const float2*)(bi + MEM + kc0);
                float2 biN = *(const float2*)(bi + 2 * MEM + kc0);
                float gR0 = aR0 + biR.x, gR1 = aR1 + biR.y;
                float gZ0 = aZ0 + biZ.x, gZ1 = aZ1 + biZ.y;
                float gN0 = aN0 + biN.x, gN1 = aN1 + biN.y;
                if ((row & 1) == 0) {
                    float r0 = sigmoidf(gR0 + bhR.x), r1 = sigmoidf(gR1 + bhR.y);
                    float z0 = sigmoidf(gZ0 + bhZ.x), z1 = sigmoidf(gZ1 + bhZ.y);
                    float n0 = tanh_apx(gN0 + r0 * bhN.x), n1 = tanh_apx(gN1 + r1 * bhN.y);
                    float h10 = (1.0f - z0) * n0, h11 = (1.0f - z1) * n1;
                    size_t idx = (size_t)(row >> 1) * MEM + kc0;
                    *(float2*)(g_H32 + idx) = make_float2(h10, h11);
                    *(__half2*)(g_H16 + idx) = __floats2half2_rn(h10, h11);
                } else {
                    __half* d = g_Gi16 + (size_t)row * G3 + kc0;
                    *(__half2*)(d)           = __floats2half2_rn(gR0, gR1);
                    *(__half2*)(d + MEM)     = __floats2half2_rn(gZ0, gZ1);
                    *(__half2*)(d + 2 * MEM) = __floats2half2_rn(gN0, gN1);
                }
            } else if (MODE == 2) {
                const __half* gi = g_Gi16 + (size_t)(2 * row + 1) * G3 + kc0;
                float2 gR = __half22float2(*(const __half2*)(gi));
                float2 gZ = __half22float2(*(const __half2*)(gi + MEM));
                float2 gN = __half22float2(*(const __half2*)(gi + 2 * MEM));
                float r0 = sigmoidf(gR.x + aR0 + bhR.x), r1 = sigmoidf(gR.y + aR1 + bhR.y);
                float z0 = sigmoidf(gZ.x + aZ0 + bhZ.x), z1 = sigmoidf(gZ.y + aZ1 + bhZ.y);
                float n0 = tanh_apx(gN.x + r0 * (aN0 + bhN.x));
                float n1 = tanh_apx(gN.y + r1 * (aN1 + bhN.y));
                size_t idx = (size_t)row * MEM + kc0;
                float2 hp = *(const float2*)(g_H32 + idx);
                float h20 = (1.0f - z0) * n0 + z0 * hp.x;
                float h21 = (1.0f - z1) * n1 + z1 * hp.y;
                *(float2*)(g_H232 + idx) = make_float2(h20, h21);
                *(__half2*)(g_H216 + idx) = __floats2half2_rn(h20, h21);
            } else {
                float2 biR = *(const float2*)(bi + kc0);
                float2 biZ = *(const float2*)(bi + MEM + kc0);
                float2 biN = *(const float2*)(bi + 2 * MEM + kc0);
                float r0 = sigmoidf(biR.x + aR0 + bhR.x), r1 = sigmoidf(biR.y + aR1 + bhR.y);
                float z0 = sigmoidf(biZ.x + aZ0 + bhZ.x), z1 = sigmoidf(biZ.y + aZ1 + bhZ.y);
                float n0 = tanh_apx(biN.x + r0 * (aN0 + bhN.x));
                float n1 = tanh_apx(biN.y + r1 * (aN1 + bhN.y));
                float2 hp = *(const float2*)(g_H232 + (size_t)row * MEM + kc0);
                float s0 = (1.0f - z0) * n0 + z0 * hp.x;
                float s1 = (1.0f - z1) * n1 + z1 * hp.y;
                *(__half2*)(g_states16 + (size_t)(row + nlvl - 1) * MEM + kc0) =
                    __floats2half2_rn(s0, s1);
                if (nlvl == 1) { out[kc0] = s0; out[kc0 + 1] = s1; }
            }
        }

    cudaTriggerProgrammaticLaunchCompletion();
}

// ---------------- prep: build fp16 operands ------------------------------------
__global__ void prep_half(const float* __restrict__ embs, const float* __restrict__ tags,
                          const float* __restrict__ lw, const float* __restrict__ cwi,
                          const float* __restrict__ cwh, const float* __restrict__ nw) {
    const int64_t stride = (int64_t)gridDim.x * blockDim.x;
    const int64_t t0 = blockIdx.x * (int64_t)blockDim.x + threadIdx.x;
    for (int64_t i = t0; i < (int64_t)LEAVES * LEAF_IN; i += stride) {
        int r = (int)(i / LEAF_IN), c = (int)(i % LEAF_IN);
        float v = (c < WORD) ? embs[(size_t)r * WORD + c]
                             : tags[(size_t)(LEAVES - 1 + r) * TAG + (c - WORD)];
        g_leafx16[i] = __float2half(v);
    }
    for (int64_t i = t0; i < (int64_t)NNODES * 2 * TAG; i += stride) {
        int id = (int)(i / (2 * TAG)), c = (int)(i % (2 * TAG));
        int pid = (id > 0) ? ((id - 1) >> 1) : 0;
        float v = (c < TAG) ? tags[(size_t)id * TAG + c]
                            : tags[(size_t)pid * TAG + (c - TAG)];
        g_tagp16[i] = __float2half(v);
    }
    for (int64_t i = t0; i < (int64_t)G3 * LEAF_IN; i += stride) g_Wl16[i]  = __float2half(lw[i]);
    for (int64_t i = t0; i < (int64_t)G3 * CH_IN;  i += stride) g_Wci16[i] = __float2half(cwi[i]);
    for (int64_t i = t0; i < (int64_t)G3 * MEM;    i += stride) g_Wch16[i] = __float2half(cwh[i]);
    for (int64_t i = t0; i < (int64_t)G3 * MEM;    i += stride) g_Wn16[i]  = __float2half(nw[i]);
    cudaTriggerProgrammaticLaunchCompletion();
}

// ---------------- host driver ------------------------------------------------
template<typename F, typename... Args>
static void launch_pdl(F f, dim3 g, dim3 b, size_t smem, Args... args) {
    cudaLaunchConfig_t cfg = {};
    cfg.gridDim = g;
    cfg.blockDim = b;
    cfg.dynamicSmemBytes = smem;
    cfg.stream = 0;
    cudaLaunchAttribute attr[1];
    attr[0].id = cudaLaunchAttributeProgrammaticStreamSerialization;
    attr[0].val.programmaticStreamSerializationAllowed = 1;
    cfg.attrs = attr;
    cfg.numAttrs = 1;
    cudaLaunchKernelEx(&cfg, f, args...);
}

extern "C" void kernel_launch(void* const* d_in, const int* in_sizes, int n_in,
                              void* d_out, int out_size) {
    const float* embs    = (const float*)d_in[0];
    const float* tags    = (const float*)d_in[1];
    const float* leaf_Wi = (const float*)d_in[2];
    const float* leaf_bi = (const float*)d_in[4];
    const float* leaf_bh = (const float*)d_in[5];
    const float* node_Wh = (const float*)d_in[7];
    const float* node_bi = (const float*)d_in[8];
    const float* node_bh = (const float*)d_in[9];
    const float* ch_Wi   = (const float*)d_in[10];
    const float* ch_Wh   = (const float*)d_in[11];
    const float* ch_bi   = (const float*)d_in[12];
    const float* ch_bh   = (const float*)d_in[13];

    __half *pWl, *pWci, *pWch, *pWn;
    cudaGetSymbolAddress((void**)&pWl,  g_Wl16);
    cudaGetSymbolAddress((void**)&pWci, g_Wci16);
    cudaGetSymbolAddress((void**)&pWch, g_Wch16);
    cudaGetSymbolAddress((void**)&pWn,  g_Wn16);

    cudaFuncSetAttribute(gemm_gru<0,LEAF_IN>, cudaFuncAttributeMaxDynamicSharedMemorySize, SMEM_SZ);
    cudaFuncSetAttribute(gemm_gru<1,CH_IN>,   cudaFuncAttributeMaxDynamicSharedMemorySize, SMEM_SZ);
    cudaFuncSetAttribute(gemm_gru<2,MEM>,     cudaFuncAttributeMaxDynamicSharedMemorySize, SMEM_SZ);
    cudaFuncSetAttribute(gemm_gru<3,MEM>,     cudaFuncAttributeMaxDynamicSharedMemorySize, SMEM_SZ);

    auto grid = [](int M) { return dim3(MEM / 32, (M + 63) / 64); };
    float* out = (float*)d_out;

    prep_half<<<1024, 256>>>(embs, tags, leaf_Wi, ch_Wi, ch_Wh, node_Wh);

    launch_pdl(gemm_gru<0,LEAF_IN>, grid(LEAVES), dim3(256), SMEM_SZ,
               (const __half*)pWl, leaf_bi, leaf_bh, LEAVES, 0, out);
    for (int lvl = DEPTH - 1; lvl >= 0; --lvl) {
        int n = 1 << lvl;
        launch_pdl(gemm_gru<1,CH_IN>, grid(2 * n), dim3(256), SMEM_SZ,
                   (const __half*)pWci, ch_bi, ch_bh, 2 * n, n, out);
        launch_pdl(gemm_gru<2,MEM>, grid(n), dim3(256), SMEM_SZ,
                   (const __half*)pWch, ch_bi, ch_bh, n, n, out);
        launch_pdl(gemm_gru<3,MEM>, grid(n), dim3(256), SMEM_SZ,
                   (const __half*)pWn, node_bi, node_bh, n, n, out);
    }
}